// round 15
// baseline (speedup 1.0000x reference)
#include <cuda_runtime.h>
#include <cuda_bf16.h>
#include <cstdint>

#define THREADS 128
#define HID 100
#define NC 30
#define SD 10
#define BETA_F 3.0f
#define MAXA_F 5.0f

// ---- precomputed mma B fragments (uint4 = hi b0,b1, lo b0,b1) ----
#define NFRAG2_LOC (7 * 8 * 32)    // layer2 loc: 7 k-chunks x 8 n-tiles x 32 lanes
#define NFRAG2_VAL (7 * 4 * 32)    // layer2 val (columns PERMUTED, see prep)
#define NFRAG1     (13 * 32)       // layer1 (per branch): 13 n-tiles x 32 lanes
#define NFRAG_TOT  (NFRAG2_LOC + NFRAG2_VAL + 2 * NFRAG1)
__device__ uint4 d_bfrag[NFRAG_TOT];

__device__ __forceinline__ float tanh_fast(float x) {
    float e = __expf(2.0f * x);
    return 1.0f - __fdividef(2.0f, e + 1.0f);
}
__device__ __forceinline__ void mma_bf16(float* c, const uint32_t* A,
                                         uint32_t b0, uint32_t b1) {
    asm volatile(
        "mma.sync.aligned.m16n8k16.row.col.f32.bf16.bf16.f32 "
        "{%0,%1,%2,%3}, {%4,%5,%6,%7}, {%8,%9}, {%0,%1,%2,%3};"
        : "+f"(c[0]), "+f"(c[1]), "+f"(c[2]), "+f"(c[3])
        : "r"(A[0]), "r"(A[1]), "r"(A[2]), "r"(A[3]), "r"(b0), "r"(b1));
}
// 3-term split mma: hi*hi + hi*lo + lo*hi
__device__ __forceinline__ void mma3(float* c, const uint32_t* Ah,
                                     const uint32_t* Al, uint4 b) {
    mma_bf16(c, Ah, b.x, b.y);
    mma_bf16(c, Ah, b.z, b.w);
    mma_bf16(c, Al, b.x, b.y);
}
__device__ __forceinline__ uint32_t cvt2(float hi, float lo) {
    uint32_t r;
    asm("cvt.rn.bf16x2.f32 %0, %1, %2;" : "=r"(r) : "f"(hi), "f"(lo));
    return r;
}
// split (vx, vy) -> (hi bf16x2, lo bf16x2)
__device__ __forceinline__ void split2(float vx, float vy, uint32_t& h, uint32_t& l) {
    h = cvt2(vy, vx);
    float lx = vx - __uint_as_float(h << 16);
    float ly = vy - __uint_as_float(h & 0xFFFF0000u);
    l = cvt2(ly, lx);
}
// relu + split C tile pair -> A fragments
__device__ __forceinline__ void relu_split(const float (&C)[2][4],
                                           uint32_t (&Ah)[4], uint32_t (&Al)[4]) {
    #pragma unroll
    for (int h = 0; h < 2; h++) {
        float v0 = fmaxf(C[h][0], 0.0f);
        float v1 = fmaxf(C[h][1], 0.0f);
        float v2 = fmaxf(C[h][2], 0.0f);
        float v3 = fmaxf(C[h][3], 0.0f);
        split2(v0, v1, Ah[2 * h + 0], Al[2 * h + 0]);   // row lr
        split2(v2, v3, Ah[2 * h + 1], Al[2 * h + 1]);   // row lr+8
    }
}

// ---- prep: build all B fragments in mma lane order ----
// Layer1 frags: hidden unit n, K rows = s dims 0..9, k=10 = bias (via s ones col).
//   n == 100 gets bias 1.0 / weights 0 => h_100 = relu(1) = 1 (feeds the
//   layer-2 bias row k=100). cols 101+ all zero.
// Val layer2 columns are PERMUTED so the val C-fragment's lane ownership
// matches the loc C-fragment's centroid ownership:
//   tile position p = 2*lq + e carries centroid n = 8*tv + 4*(p&1) + (p>>1)
// => lane lq's cv[tv][e] is the value of centroid n = 4*(2tv+e)+lq, exactly the
//    centroid whose ew lane lq computed in the loc epilogue.
extern "C" __global__ void prep_kernel(const float* __restrict__ W1,
                                       const float* __restrict__ b1,
                                       const float* __restrict__ W2,
                                       const float* __restrict__ b2,
                                       const float* __restrict__ L1,
                                       const float* __restrict__ bl1,
                                       const float* __restrict__ WL2,
                                       const float* __restrict__ bL2) {
    int t = blockIdx.x * blockDim.x + threadIdx.x;
    int stride = gridDim.x * blockDim.x;
    for (int idx = t; idx < NFRAG_TOT; idx += stride) {
        float v[4];
        if (idx < NFRAG2_LOC + NFRAG2_VAL) {            // ---- layer2 frags ----
            bool isloc = idx < NFRAG2_LOC;
            int rel = isloc ? idx : idx - NFRAG2_LOC;
            int lane = rel & 31;
            int f = rel >> 5;
            int nt = isloc ? 8 : 4;
            int q = f / nt, tn = f % nt;
            int k0 = q * 16 + 2 * (lane & 3);
            int n;
            if (isloc) {
                n = tn * 8 + (lane >> 2);               // natural order
            } else {
                int p = lane >> 2;                      // col position in tile
                n = tn * 8 + 4 * (p & 1) + (p >> 1);    // permuted centroid idx
            }
            #pragma unroll
            for (int e = 0; e < 4; e++) {
                int k = k0 + (e >> 1) * 8 + (e & 1);
                float x = 0.0f;
                if (isloc) {
                    if (n < 60) {
                        if (k < HID)       x = WL2[(n >> 1) * 200 + k * 2 + (n & 1)];
                        else if (k == HID) x = bL2[n];
                    }
                } else {
                    if (n < NC) {
                        if (k < HID)       x = W2[k * NC + n];
                        else if (k == HID) x = b2[n];
                    }
                }
                v[e] = x;
            }
        } else {                                        // ---- layer1 frags ----
            int rel = idx - (NFRAG2_LOC + NFRAG2_VAL);
            bool isloc = rel < NFRAG1;
            if (!isloc) rel -= NFRAG1;
            int lane = rel & 31;
            int tn = rel >> 5;                          // 0..12
            int k0 = 2 * (lane & 3);
            int n  = tn * 8 + (lane >> 2);              // hidden unit j
            const float* Wm = isloc ? L1 : W1;
            const float* bm = isloc ? bl1 : b1;
            #pragma unroll
            for (int e = 0; e < 4; e++) {
                int k = k0 + (e >> 1) * 8 + (e & 1);
                float x = 0.0f;
                if (n < HID) {
                    if (k < SD)       x = Wm[k * HID + n];
                    else if (k == SD) x = bm[n];        // layer1 bias via s ones-col
                } else if (n == HID && k == SD) {
                    x = 1.0f;                           // h_100 = 1 (l2 bias row)
                }
                v[e] = x;
            }
        }
        unsigned short hb[4], lb[4];
        #pragma unroll
        for (int e = 0; e < 4; e++) {
            __nv_bfloat16 h = __float2bfloat16(v[e]);
            hb[e] = __bfloat16_as_ushort(h);
            lb[e] = __bfloat16_as_ushort(__float2bfloat16(v[e] - __bfloat162float(h)));
        }
        uint4 o;
        o.x = (uint32_t)hb[0] | ((uint32_t)hb[1] << 16);
        o.y = (uint32_t)hb[2] | ((uint32_t)hb[3] << 16);
        o.z = (uint32_t)lb[0] | ((uint32_t)lb[1] << 16);
        o.w = (uint32_t)lb[2] | ((uint32_t)lb[3] << 16);
        d_bfrag[idx] = o;
    }
}

extern "C" __global__ void __launch_bounds__(THREADS, 6)
net_kernel(const float* __restrict__ s, const float* __restrict__ a,
           float* __restrict__ out, int B)
{
    const int t = threadIdx.x;
    const int lane = t & 31;
    const int warp = t >> 5;
    const int lq = lane & 3, lr = lane >> 2;

    const int base = blockIdx.x * 64 + warp * 16;

    // ---- A fragments of s (K=16: 10 inputs + ones col @10 for l1 bias) ----
    uint32_t Ash[4], Asl[4];
    #pragma unroll
    for (int rr = 0; rr < 2; rr++) {              // rr 0: row lr, 1: row lr+8
        int r = base + lr + rr * 8;
        r = r < B ? r : B - 1;
        const float* sr = s + (size_t)r * SD;
        float2 v01 = *(const float2*)(sr + 2 * lq);       // cols 2lq, 2lq+1
        float2 v23;                                       // cols 8+2lq, 9+2lq
        if (lq == 0)      v23 = *(const float2*)(sr + 8);
        else if (lq == 1) v23 = make_float2(1.0f, 0.0f);  // ones col @10
        else              v23 = make_float2(0.0f, 0.0f);
        split2(v01.x, v01.y, Ash[rr],     Asl[rr]);
        split2(v23.x, v23.y, Ash[2 + rr], Asl[2 + rr]);
    }

    const uint4* bf2_loc = d_bfrag;
    const uint4* bf2_val = d_bfrag + NFRAG2_LOC;
    const uint4* bf1_loc = d_bfrag + NFRAG2_LOC + NFRAG2_VAL;
    const uint4* bf1_val = bf1_loc + NFRAG1;

    // ---- fused dual-branch GEMM, live-range-minimized ordering ----
    float cl[8][4], cv[4][4];
    #pragma unroll
    for (int tn = 0; tn < 8; tn++)
        #pragma unroll
        for (int e = 0; e < 4; e++) cl[tn][e] = 0.0f;
    #pragma unroll
    for (int tv = 0; tv < 4; tv++)
        #pragma unroll
        for (int e = 0; e < 4; e++) cv[tv][e] = 0.0f;

    #pragma unroll
    for (int q = 0; q < 7; q++) {
        // layer1, both branches: independent mma chains fill the tensor pipe
        float Cl[2][4], Cv[2][4];
        #pragma unroll
        for (int h = 0; h < 2; h++)
            #pragma unroll
            for (int e = 0; e < 4; e++) { Cl[h][e] = 0.0f; Cv[h][e] = 0.0f; }

        mma3(Cl[0], Ash, Asl, __ldg(&bf1_loc[(2 * q) * 32 + lane]));
        mma3(Cv[0], Ash, Asl, __ldg(&bf1_val[(2 * q) * 32 + lane]));
        if (q < 6) {
            mma3(Cl[1], Ash, Asl, __ldg(&bf1_loc[(2 * q + 1) * 32 + lane]));
            mma3(Cv[1], Ash, Asl, __ldg(&bf1_val[(2 * q + 1) * 32 + lane]));
        }

        // loc split first (Cl dies), loc layer2; val split (Cv dies), val layer2
        {
            uint32_t Ahl[4], All[4];
            relu_split(Cl, Ahl, All);
            #pragma unroll
            for (int tn = 0; tn < 8; tn++) {
                uint4 b = __ldg(&bf2_loc[(q * 8 + tn) * 32 + lane]);
                mma3(cl[tn], Ahl, All, b);
            }
        }
        {
            uint32_t Ahv[4], Alv[4];
            relu_split(Cv, Ahv, Alv);
            #pragma unroll
            for (int tv = 0; tv < 4; tv++) {
                uint4 b = __ldg(&bf2_val[(q * 4 + tv) * 32 + lane]);
                mma3(cv[tv], Ahv, Alv, b);
            }
        }
    }

    float2 av0, av1;
    { int r = base + lr;     r = r < B ? r : B - 1; av0 = *(const float2*)(a + (size_t)r * 2); }
    { int r = base + lr + 8; r = r < B ? r : B - 1; av1 = *(const float2*)(a + (size_t)r * 2); }

    // ---- loc epilogue: centroids -> ew (registers) + den ----
    float ew0[8], ew1[8];
    float den0 = 0.0f, den1 = 0.0f;
    #pragma unroll
    for (int tn = 0; tn < 8; tn++) {
        int n = tn * 4 + lq;
        float e0 = 0.0f, e1 = 0.0f;
        if (n < NC) {
            float px = MAXA_F * tanh_fast(cl[tn][0]);
            float py = MAXA_F * tanh_fast(cl[tn][1]);
            float dx = px - av0.x, dy = py - av0.y;
            e0 = __expf(-BETA_F * sqrtf(fmaf(dx, dx, dy * dy)));
            px = MAXA_F * tanh_fast(cl[tn][2]);
            py = MAXA_F * tanh_fast(cl[tn][3]);
            dx = px - av1.x; dy = py - av1.y;
            e1 = __expf(-BETA_F * sqrtf(fmaf(dx, dx, dy * dy)));
        }
        ew0[tn] = e0;
        ew1[tn] = e1;
        den0 += e0;
        den1 += e1;
    }
    den0 += __shfl_xor_sync(0xFFFFFFFFu, den0, 1);
    den0 += __shfl_xor_sync(0xFFFFFFFFu, den0, 2);
    den1 += __shfl_xor_sync(0xFFFFFFFFu, den1, 1);
    den1 += __shfl_xor_sync(0xFFFFFFFFu, den1, 2);

    // ---- val epilogue: num = sum ew*v, all in registers (permuted cols) ----
    float num0 = 0.0f, num1 = 0.0f;
    #pragma unroll
    for (int tv = 0; tv < 4; tv++) {
        num0 += ew0[2 * tv] * cv[tv][0] + ew0[2 * tv + 1] * cv[tv][1];
        num1 += ew1[2 * tv] * cv[tv][2] + ew1[2 * tv + 1] * cv[tv][3];
    }
    num0 += __shfl_xor_sync(0xFFFFFFFFu, num0, 1);
    num0 += __shfl_xor_sync(0xFFFFFFFFu, num0, 2);
    num1 += __shfl_xor_sync(0xFFFFFFFFu, num1, 1);
    num1 += __shfl_xor_sync(0xFFFFFFFFu, num1, 2);
    if (lq == 0) {
        int r0 = base + lr, r1 = base + lr + 8;
        if (r0 < B) out[r0] = num0 / den0;
        if (r1 < B) out[r1] = num1 / den1;
    }
}

extern "C" void kernel_launch(void* const* d_in, const int* in_sizes, int n_in,
                              void* d_out, int out_size) {
    const float* s   = (const float*)d_in[0];
    const float* a   = (const float*)d_in[1];
    const float* W1  = (const float*)d_in[2];
    const float* b1  = (const float*)d_in[3];
    const float* W2  = (const float*)d_in[4];
    const float* b2  = (const float*)d_in[5];
    const float* L1  = (const float*)d_in[6];
    const float* bl1 = (const float*)d_in[7];
    const float* WL2 = (const float*)d_in[8];
    const float* bL2 = (const float*)d_in[9];
    float* out = (float*)d_out;

    const int B = in_sizes[0] / SD;
    const int blocks = (B + 63) / 64;

    prep_kernel<<<8, 256>>>(W1, b1, W2, b2, L1, bl1, WL2, bL2);

    net_kernel<<<blocks, THREADS>>>(s, a, out, B);
}

// round 16
// speedup vs baseline: 1.1027x; 1.1027x over previous
#include <cuda_runtime.h>
#include <cuda_bf16.h>
#include <cstdint>

#define THREADS 128
#define HID 100
#define NC 30
#define SD 10
#define BETA_F 3.0f
#define MAXA_F 5.0f

// ---- precomputed mma B fragments (uint4 = hi b0,b1, lo b0,b1) ----
#define NFRAG2_LOC (7 * 8 * 32)    // layer2 loc: 7 k-chunks x 8 n-tiles x 32 lanes
#define NFRAG2_VAL (7 * 4 * 32)    // layer2 val (columns PERMUTED, see prep)
#define NFRAG1     (13 * 32)       // layer1 (per branch): 13 n-tiles x 32 lanes
#define NFRAG_TOT  (NFRAG2_LOC + NFRAG2_VAL + 2 * NFRAG1)
__device__ uint4 d_bfrag[NFRAG_TOT];

__device__ __forceinline__ float tanh_fast(float x) {
    float e = __expf(2.0f * x);
    return 1.0f - __fdividef(2.0f, e + 1.0f);
}
__device__ __forceinline__ void mma_bf16(float* c, const uint32_t* A,
                                         uint32_t b0, uint32_t b1) {
    asm volatile(
        "mma.sync.aligned.m16n8k16.row.col.f32.bf16.bf16.f32 "
        "{%0,%1,%2,%3}, {%4,%5,%6,%7}, {%8,%9}, {%0,%1,%2,%3};"
        : "+f"(c[0]), "+f"(c[1]), "+f"(c[2]), "+f"(c[3])
        : "r"(A[0]), "r"(A[1]), "r"(A[2]), "r"(A[3]), "r"(b0), "r"(b1));
}
// zero-C variant: d = A*B + 0 (no accumulator init needed)
__device__ __forceinline__ void mma_bf16_zc(float* c, const uint32_t* A,
                                            uint32_t b0, uint32_t b1) {
    asm volatile(
        "mma.sync.aligned.m16n8k16.row.col.f32.bf16.bf16.f32 "
        "{%0,%1,%2,%3}, {%4,%5,%6,%7}, {%8,%9}, {%10,%11,%12,%13};"
        : "=f"(c[0]), "=f"(c[1]), "=f"(c[2]), "=f"(c[3])
        : "r"(A[0]), "r"(A[1]), "r"(A[2]), "r"(A[3]), "r"(b0), "r"(b1),
          "f"(0.0f), "f"(0.0f), "f"(0.0f), "f"(0.0f));
}
// 3-term split mma: hi*hi + hi*lo + lo*hi (accumulating)
__device__ __forceinline__ void mma3(float* c, const uint32_t* Ah,
                                     const uint32_t* Al, uint4 b) {
    mma_bf16(c, Ah, b.x, b.y);
    mma_bf16(c, Ah, b.z, b.w);
    mma_bf16(c, Al, b.x, b.y);
}
// 3-term split mma, overwriting C (first accumulation)
__device__ __forceinline__ void mma3_zc(float* c, const uint32_t* Ah,
                                        const uint32_t* Al, uint4 b) {
    mma_bf16_zc(c, Ah, b.x, b.y);
    mma_bf16(c, Ah, b.z, b.w);
    mma_bf16(c, Al, b.x, b.y);
}
__device__ __forceinline__ uint32_t cvt2(float hi, float lo) {
    uint32_t r;
    asm("cvt.rn.bf16x2.f32 %0, %1, %2;" : "=r"(r) : "f"(hi), "f"(lo));
    return r;
}
// split (vx, vy) -> (hi bf16x2, lo bf16x2)
__device__ __forceinline__ void split2(float vx, float vy, uint32_t& h, uint32_t& l) {
    h = cvt2(vy, vx);
    float lx = vx - __uint_as_float(h << 16);
    float ly = vy - __uint_as_float(h & 0xFFFF0000u);
    l = cvt2(ly, lx);
}
// relu + split C tile pair -> A fragments
__device__ __forceinline__ void relu_split(const float (&C)[2][4],
                                           uint32_t (&Ah)[4], uint32_t (&Al)[4]) {
    #pragma unroll
    for (int h = 0; h < 2; h++) {
        float v0 = fmaxf(C[h][0], 0.0f);
        float v1 = fmaxf(C[h][1], 0.0f);
        float v2 = fmaxf(C[h][2], 0.0f);
        float v3 = fmaxf(C[h][3], 0.0f);
        split2(v0, v1, Ah[2 * h + 0], Al[2 * h + 0]);   // row lr
        split2(v2, v3, Ah[2 * h + 1], Al[2 * h + 1]);   // row lr+8
    }
}

// ---- prep: build all B fragments in mma lane order ----
// Layer1 frags: hidden unit n, K rows = s dims 0..9, k=10 = bias (via s ones col).
//   n == 100 gets bias 1.0 / weights 0 => h_100 = relu(1) = 1 (feeds the
//   layer-2 bias row k=100). cols 101+ all zero.
// Val layer2 columns are PERMUTED so the val C-fragment's lane ownership
// matches the loc C-fragment's centroid ownership:
//   tile position p = 2*lq + e carries centroid n = 8*tv + 4*(p&1) + (p>>1)
// => lane lq's cv[tv][e] is the value of centroid n = 4*(2tv+e)+lq, exactly the
//    centroid whose ew lane lq computed in the loc epilogue.
extern "C" __global__ void prep_kernel(const float* __restrict__ W1,
                                       const float* __restrict__ b1,
                                       const float* __restrict__ W2,
                                       const float* __restrict__ b2,
                                       const float* __restrict__ L1,
                                       const float* __restrict__ bl1,
                                       const float* __restrict__ WL2,
                                       const float* __restrict__ bL2) {
    int t = blockIdx.x * blockDim.x + threadIdx.x;
    int stride = gridDim.x * blockDim.x;
    for (int idx = t; idx < NFRAG_TOT; idx += stride) {
        float v[4];
        if (idx < NFRAG2_LOC + NFRAG2_VAL) {            // ---- layer2 frags ----
            bool isloc = idx < NFRAG2_LOC;
            int rel = isloc ? idx : idx - NFRAG2_LOC;
            int lane = rel & 31;
            int f = rel >> 5;
            int nt = isloc ? 8 : 4;
            int q = f / nt, tn = f % nt;
            int k0 = q * 16 + 2 * (lane & 3);
            int n;
            if (isloc) {
                n = tn * 8 + (lane >> 2);               // natural order
            } else {
                int p = lane >> 2;                      // col position in tile
                n = tn * 8 + 4 * (p & 1) + (p >> 1);    // permuted centroid idx
            }
            #pragma unroll
            for (int e = 0; e < 4; e++) {
                int k = k0 + (e >> 1) * 8 + (e & 1);
                float x = 0.0f;
                if (isloc) {
                    if (n < 60) {
                        if (k < HID)       x = WL2[(n >> 1) * 200 + k * 2 + (n & 1)];
                        else if (k == HID) x = bL2[n];
                    }
                } else {
                    if (n < NC) {
                        if (k < HID)       x = W2[k * NC + n];
                        else if (k == HID) x = b2[n];
                    }
                }
                v[e] = x;
            }
        } else {                                        // ---- layer1 frags ----
            int rel = idx - (NFRAG2_LOC + NFRAG2_VAL);
            bool isloc = rel < NFRAG1;
            if (!isloc) rel -= NFRAG1;
            int lane = rel & 31;
            int tn = rel >> 5;                          // 0..12
            int k0 = 2 * (lane & 3);
            int n  = tn * 8 + (lane >> 2);              // hidden unit j
            const float* Wm = isloc ? L1 : W1;
            const float* bm = isloc ? bl1 : b1;
            #pragma unroll
            for (int e = 0; e < 4; e++) {
                int k = k0 + (e >> 1) * 8 + (e & 1);
                float x = 0.0f;
                if (n < HID) {
                    if (k < SD)       x = Wm[k * HID + n];
                    else if (k == SD) x = bm[n];        // layer1 bias via s ones-col
                } else if (n == HID && k == SD) {
                    x = 1.0f;                           // h_100 = 1 (l2 bias row)
                }
                v[e] = x;
            }
        }
        unsigned short hb[4], lb[4];
        #pragma unroll
        for (int e = 0; e < 4; e++) {
            __nv_bfloat16 h = __float2bfloat16(v[e]);
            hb[e] = __bfloat16_as_ushort(h);
            lb[e] = __bfloat16_as_ushort(__float2bfloat16(v[e] - __bfloat162float(h)));
        }
        uint4 o;
        o.x = (uint32_t)hb[0] | ((uint32_t)hb[1] << 16);
        o.y = (uint32_t)hb[2] | ((uint32_t)hb[3] << 16);
        o.z = (uint32_t)lb[0] | ((uint32_t)lb[1] << 16);
        o.w = (uint32_t)lb[2] | ((uint32_t)lb[3] << 16);
        d_bfrag[idx] = o;
    }
}

// one branch, 16 rows/warp: layer1 (tensor) -> register relu/split -> layer2
template<int NT>
__device__ __forceinline__ void branch_gemm(
    const uint4* __restrict__ bf1, const uint4* __restrict__ bf2,
    const uint32_t (&Ash)[4], const uint32_t (&Asl)[4],
    int lane, float (&c)[NT][4])
{
    #pragma unroll
    for (int q = 0; q < 7; q++) {
        // ---- layer1: hidden cols [16q, 16q+16), no accumulator init ----
        float C[2][4];
        mma3_zc(C[0], Ash, Asl, __ldg(&bf1[(2 * q) * 32 + lane]));
        if (q < 6) {
            mma3_zc(C[1], Ash, Asl, __ldg(&bf1[(2 * q + 1) * 32 + lane]));
        } else {
            C[1][0] = 0.0f; C[1][1] = 0.0f; C[1][2] = 0.0f; C[1][3] = 0.0f;
        }
        // ---- relu + split -> layer2 A fragments (registers only) ----
        uint32_t Ah[4], Al[4];
        relu_split(C, Ah, Al);
        // ---- layer2 (q==0 overwrites c, no init needed) ----
        #pragma unroll
        for (int tn = 0; tn < NT; tn++) {
            uint4 b = __ldg(&bf2[(q * NT + tn) * 32 + lane]);
            if (q == 0) mma3_zc(c[tn], Ah, Al, b);
            else        mma3(c[tn], Ah, Al, b);
        }
    }
}

extern "C" __global__ void __launch_bounds__(THREADS, 6)
net_kernel(const float* __restrict__ s, const float* __restrict__ a,
           float* __restrict__ out, int B)
{
    const int t = threadIdx.x;
    const int lane = t & 31;
    const int warp = t >> 5;
    const int lq = lane & 3, lr = lane >> 2;

    const int base = blockIdx.x * 64 + warp * 16;

    // ---- A fragments of s (K=16: 10 inputs + ones col @10 for l1 bias) ----
    uint32_t Ash[4], Asl[4];
    #pragma unroll
    for (int rr = 0; rr < 2; rr++) {              // rr 0: row lr, 1: row lr+8
        int r = base + lr + rr * 8;
        r = r < B ? r : B - 1;
        const float* sr = s + (size_t)r * SD;
        float2 v01 = *(const float2*)(sr + 2 * lq);       // cols 2lq, 2lq+1
        float2 v23;                                       // cols 8+2lq, 9+2lq
        if (lq == 0)      v23 = *(const float2*)(sr + 8);
        else if (lq == 1) v23 = make_float2(1.0f, 0.0f);  // ones col @10
        else              v23 = make_float2(0.0f, 0.0f);
        split2(v01.x, v01.y, Ash[rr],     Asl[rr]);
        split2(v23.x, v23.y, Ash[2 + rr], Asl[2 + rr]);
    }

    // ---- hoist action-vector loads: latency hidden under both GEMMs ----
    float2 av0, av1;
    { int r = base + lr;     r = r < B ? r : B - 1; av0 = __ldg((const float2*)(a + (size_t)r * 2)); }
    { int r = base + lr + 8; r = r < B ? r : B - 1; av1 = __ldg((const float2*)(a + (size_t)r * 2)); }

    const uint4* bf2_loc = d_bfrag;
    const uint4* bf2_val = d_bfrag + NFRAG2_LOC;
    const uint4* bf1_loc = d_bfrag + NFRAG2_LOC + NFRAG2_VAL;
    const uint4* bf1_val = bf1_loc + NFRAG1;

    // ---- loc branch: 30 centroid (x,y) pairs in N=64 ----
    float cl[8][4];
    branch_gemm<8>(bf1_loc, bf2_loc, Ash, Asl, lane, cl);

    // ---- loc epilogue: centroids -> ew (registers) + den ----
    float ew0[8], ew1[8];
    float den0 = 0.0f, den1 = 0.0f;
    #pragma unroll
    for (int tn = 0; tn < 8; tn++) {
        float e0, e1;
        if (tn < 7) {                   // n = 4tn+lq <= 27: always active
            float px = MAXA_F * tanh_fast(cl[tn][0]);
            float py = MAXA_F * tanh_fast(cl[tn][1]);
            float dx = px - av0.x, dy = py - av0.y;
            e0 = __expf(-BETA_F * sqrtf(fmaf(dx, dx, dy * dy)));
            px = MAXA_F * tanh_fast(cl[tn][2]);
            py = MAXA_F * tanh_fast(cl[tn][3]);
            dx = px - av1.x; dy = py - av1.y;
            e1 = __expf(-BETA_F * sqrtf(fmaf(dx, dx, dy * dy)));
        } else {                        // tn==7: n = 28+lq, active only lq<2
            e0 = 0.0f; e1 = 0.0f;
            if (lq < 2) {
                float px = MAXA_F * tanh_fast(cl[tn][0]);
                float py = MAXA_F * tanh_fast(cl[tn][1]);
                float dx = px - av0.x, dy = py - av0.y;
                e0 = __expf(-BETA_F * sqrtf(fmaf(dx, dx, dy * dy)));
                px = MAXA_F * tanh_fast(cl[tn][2]);
                py = MAXA_F * tanh_fast(cl[tn][3]);
                dx = px - av1.x; dy = py - av1.y;
                e1 = __expf(-BETA_F * sqrtf(fmaf(dx, dx, dy * dy)));
            }
        }
        ew0[tn] = e0;
        ew1[tn] = e1;
        den0 += e0;
        den1 += e1;
    }
    den0 += __shfl_xor_sync(0xFFFFFFFFu, den0, 1);
    den0 += __shfl_xor_sync(0xFFFFFFFFu, den0, 2);
    den1 += __shfl_xor_sync(0xFFFFFFFFu, den1, 1);
    den1 += __shfl_xor_sync(0xFFFFFFFFu, den1, 2);

    // ---- val branch: 30 values in N=32, columns pre-permuted so that
    //      cv[tv][e]   = value of centroid n = 4*(2tv+e)+lq   (row lr)
    //      cv[tv][2+e] = same centroid, row lr+8
    float cv[4][4];
    branch_gemm<4>(bf1_val, bf2_val, Ash, Asl, lane, cv);

    // ---- val epilogue: num = sum ew*v, all in registers ----
    float num0 = 0.0f, num1 = 0.0f;
    #pragma unroll
    for (int tv = 0; tv < 4; tv++) {
        num0 += ew0[2 * tv] * cv[tv][0] + ew0[2 * tv + 1] * cv[tv][1];
        num1 += ew1[2 * tv] * cv[tv][2] + ew1[2 * tv + 1] * cv[tv][3];
    }
    num0 += __shfl_xor_sync(0xFFFFFFFFu, num0, 1);
    num0 += __shfl_xor_sync(0xFFFFFFFFu, num0, 2);
    num1 += __shfl_xor_sync(0xFFFFFFFFu, num1, 1);
    num1 += __shfl_xor_sync(0xFFFFFFFFu, num1, 2);
    if (lq == 0) {
        int r0 = base + lr, r1 = base + lr + 8;
        if (r0 < B) out[r0] = num0 / den0;
        if (r1 < B) out[r1] = num1 / den1;
    }
}

extern "C" void kernel_launch(void* const* d_in, const int* in_sizes, int n_in,
                              void* d_out, int out_size) {
    const float* s   = (const float*)d_in[0];
    const float* a   = (const float*)d_in[1];
    const float* W1  = (const float*)d_in[2];
    const float* b1  = (const float*)d_in[3];
    const float* W2  = (const float*)d_in[4];
    const float* b2  = (const float*)d_in[5];
    const float* L1  = (const float*)d_in[6];
    const float* bl1 = (const float*)d_in[7];
    const float* WL2 = (const float*)d_in[8];
    const float* bL2 = (const float*)d_in[9];
    float* out = (float*)d_out;

    const int B = in_sizes[0] / SD;
    const int blocks = (B + 63) / 64;

    prep_kernel<<<8, 256>>>(W1, b1, W2, b2, L1, bl1, WL2, bL2);

    net_kernel<<<blocks, THREADS>>>(s, a, out, B);
}